// round 3
// baseline (speedup 1.0000x reference)
#include <cuda_runtime.h>

// Problem constants
#define NROWS  65536
#define DIM    256
#define KCODES 1024

// GEMM tiling
#define BM 128
#define BN 128
#define BK 32
#define TM 8
#define TN 8
#define NTHREADS 256   // (BM/TM) * (BN/TN) = 16*16

// Device scratch (no allocations allowed; referenced directly by kernels so
// kernel_launch performs NO runtime API calls other than kernel launches).
__device__ float g_Sz[NROWS];
__device__ float g_Se[KCODES];
__device__ int   g_bestIdx[NROWS];
__device__ float g_partials[NROWS / 8];

// ---------------------------------------------------------------------------
// Row sum-of-squares for z: one warp per row (row length DIM=256 floats).
// ---------------------------------------------------------------------------
__global__ void __launch_bounds__(256)
rowsumsq_z_kernel(const float* __restrict__ x)
{
    int warp = threadIdx.x >> 5;
    int lane = threadIdx.x & 31;
    int row  = blockIdx.x * 8 + warp;

    const float4* p = reinterpret_cast<const float4*>(x + (size_t)row * DIM);
    float s = 0.0f;
#pragma unroll
    for (int t = 0; t < 2; t++) {
        float4 v = p[lane + t * 32];
        s += v.x * v.x + v.y * v.y + v.z * v.z + v.w * v.w;
    }
#pragma unroll
    for (int m = 16; m >= 1; m >>= 1)
        s += __shfl_xor_sync(0xffffffffu, s, m);
    if (lane == 0) g_Sz[row] = s;
}

__global__ void __launch_bounds__(256)
rowsumsq_e_kernel(const float* __restrict__ x)
{
    int warp = threadIdx.x >> 5;
    int lane = threadIdx.x & 31;
    int row  = blockIdx.x * 8 + warp;

    const float4* p = reinterpret_cast<const float4*>(x + (size_t)row * DIM);
    float s = 0.0f;
#pragma unroll
    for (int t = 0; t < 2; t++) {
        float4 v = p[lane + t * 32];
        s += v.x * v.x + v.y * v.y + v.z * v.z + v.w * v.w;
    }
#pragma unroll
    for (int m = 16; m >= 1; m >>= 1)
        s += __shfl_xor_sync(0xffffffffu, s, m);
    if (lane == 0) g_Se[row] = s;
}

// ---------------------------------------------------------------------------
// Fused GEMM + argmin. Each CTA: 128 rows x all 1024 codes, k-loop over 256.
// d_j computed exactly like the reference: fl(Sz + Se_j) - fl(2*dot_j),
// fp32 throughout, first-index tie-break (lexicographic (d, idx) min, which
// matches jnp.argmin first-occurrence semantics).
// ---------------------------------------------------------------------------
__global__ void __launch_bounds__(NTHREADS, 2)
argmin_kernel(const float* __restrict__ z, const float* __restrict__ e)
{
    __shared__ __align__(16) float zs[BK][BM + 4];  // transposed: zs[k][row]
    __shared__ __align__(16) float es[BK][BN + 4];  // transposed: es[k][code]
    __shared__ float ses[KCODES];

    const int tid = threadIdx.x;
    const int tx  = tid & 15;   // code-tile coordinate
    const int ty  = tid >> 4;   // row-tile coordinate
    const int rowBase = blockIdx.x * BM;

    // Cache Se in smem (read every epilogue)
#pragma unroll
    for (int t = 0; t < KCODES / NTHREADS; t++)
        ses[tid + t * NTHREADS] = g_Se[tid + t * NTHREADS];

    float szr[TM];
#pragma unroll
    for (int i = 0; i < TM; i++)
        szr[i] = g_Sz[rowBase + ty * TM + i];

    float bestd[TM];
    int   bestidx[TM];
#pragma unroll
    for (int i = 0; i < TM; i++) { bestd[i] = 3.0e38f; bestidx[i] = 0; }

    __syncthreads();

    for (int ct = 0; ct < KCODES; ct += BN) {
        float acc[TM][TN];
#pragma unroll
        for (int i = 0; i < TM; i++)
#pragma unroll
            for (int j = 0; j < TN; j++)
                acc[i][j] = 0.0f;

        for (int k0 = 0; k0 < DIM; k0 += BK) {
            // Cooperative transposed tile load: 1024 float4 per array, 4/thread
#pragma unroll
            for (int t = 0; t < 4; t++) {
                int id = tid + t * NTHREADS;
                int r  = id >> 3;   // 0..127
                int c4 = id & 7;    // 0..7
                float4 v = *reinterpret_cast<const float4*>(
                    z + (size_t)(rowBase + r) * DIM + k0 + c4 * 4);
                zs[c4 * 4 + 0][r] = v.x;
                zs[c4 * 4 + 1][r] = v.y;
                zs[c4 * 4 + 2][r] = v.z;
                zs[c4 * 4 + 3][r] = v.w;
                float4 w = *reinterpret_cast<const float4*>(
                    e + (size_t)(ct + r) * DIM + k0 + c4 * 4);
                es[c4 * 4 + 0][r] = w.x;
                es[c4 * 4 + 1][r] = w.y;
                es[c4 * 4 + 2][r] = w.z;
                es[c4 * 4 + 3][r] = w.w;
            }
            __syncthreads();

#pragma unroll 8
            for (int k = 0; k < BK; k++) {
                float zr[TM], er[TN];
                *reinterpret_cast<float4*>(&zr[0]) =
                    *reinterpret_cast<const float4*>(&zs[k][ty * TM]);
                *reinterpret_cast<float4*>(&zr[4]) =
                    *reinterpret_cast<const float4*>(&zs[k][ty * TM + 4]);
                *reinterpret_cast<float4*>(&er[0]) =
                    *reinterpret_cast<const float4*>(&es[k][tx * TN]);
                *reinterpret_cast<float4*>(&er[4]) =
                    *reinterpret_cast<const float4*>(&es[k][tx * TN + 4]);
#pragma unroll
                for (int i = 0; i < TM; i++)
#pragma unroll
                    for (int j = 0; j < TN; j++)
                        acc[i][j] = fmaf(zr[i], er[j], acc[i][j]);
            }
            __syncthreads();
        }

        // Epilogue: d = fl(Sz + Se) - fl(2*dot); strict < keeps earliest code
        // (within a thread, code indices are strictly ascending over j and ct).
#pragma unroll
        for (int j = 0; j < TN; j++) {
            int   code = ct + tx * TN + j;
            float sec  = ses[code];
#pragma unroll
            for (int i = 0; i < TM; i++) {
                float t    = szr[i] + sec;
                float dist = fmaf(-2.0f, acc[i][j], t);
                if (dist < bestd[i]) { bestd[i] = dist; bestidx[i] = code; }
            }
        }
    }

    // Cross-thread argmin over the 16 tx-threads sharing each row.
    // Lanes with the same ty are within one warp (xor masks 8..1 stay in-group).
#pragma unroll
    for (int m = 8; m >= 1; m >>= 1) {
#pragma unroll
        for (int i = 0; i < TM; i++) {
            float od = __shfl_xor_sync(0xffffffffu, bestd[i], m);
            int   oi = __shfl_xor_sync(0xffffffffu, bestidx[i], m);
            if (od < bestd[i] || (od == bestd[i] && oi < bestidx[i])) {
                bestd[i]  = od;
                bestidx[i] = oi;
            }
        }
    }

    if (tx == 0) {
#pragma unroll
        for (int i = 0; i < TM; i++)
            g_bestIdx[rowBase + ty * TM + i] = bestidx[i];
    }
}

// ---------------------------------------------------------------------------
// Gather codes, write z_q_st = z + (q - z) and indices, per-CTA loss partials.
// One warp per row; deterministic partial sums (no atomics).
// ---------------------------------------------------------------------------
__global__ void __launch_bounds__(256)
gather_kernel(const float* __restrict__ z, const float* __restrict__ e,
              float* __restrict__ out_zq, float* __restrict__ out_idx)
{
    __shared__ float ws[8];
    int warp = threadIdx.x >> 5;
    int lane = threadIdx.x & 31;
    int row  = blockIdx.x * 8 + warp;

    int idx = g_bestIdx[row];
    const float4* zp = reinterpret_cast<const float4*>(z + (size_t)row * DIM);
    const float4* qp = reinterpret_cast<const float4*>(e + (size_t)idx * DIM);
    float4*       op = reinterpret_cast<float4*>(out_zq + (size_t)row * DIM);

    float local = 0.0f;
#pragma unroll
    for (int t = 0; t < 2; t++) {
        int c = lane + t * 32;
        float4 zv = zp[c];
        float4 qv = qp[c];
        float dx = qv.x - zv.x, dy = qv.y - zv.y;
        float dz2 = qv.z - zv.z, dw = qv.w - zv.w;
        float4 o = make_float4(zv.x + dx, zv.y + dy, zv.z + dz2, zv.w + dw);
        op[c] = o;
        local += dx * dx + dy * dy + dz2 * dz2 + dw * dw;
    }
#pragma unroll
    for (int m = 16; m >= 1; m >>= 1)
        local += __shfl_xor_sync(0xffffffffu, local, m);

    if (lane == 0) {
        ws[warp] = local;
        if (out_idx) out_idx[row] = (float)idx;
    }
    __syncthreads();
    if (threadIdx.x == 0) {
        float s = 0.0f;
#pragma unroll
        for (int w = 0; w < 8; w++) s += ws[w];
        g_partials[blockIdx.x] = s;
    }
}

// ---------------------------------------------------------------------------
// Deterministic final loss reduction: loss = mean + BETA*mean, mean = sum/2^24
// ---------------------------------------------------------------------------
__global__ void __launch_bounds__(256)
finalize_kernel(float* __restrict__ out_loss)
{
    __shared__ float sm[256];
    float s = 0.0f;
    for (int i = threadIdx.x; i < NROWS / 8; i += 256)
        s += g_partials[i];
    sm[threadIdx.x] = s;
    __syncthreads();
    for (int m = 128; m >= 1; m >>= 1) {
        if (threadIdx.x < m) sm[threadIdx.x] += sm[threadIdx.x + m];
        __syncthreads();
    }
    if (threadIdx.x == 0) {
        float mean = sm[0] / 16777216.0f;          // exact power-of-two divide
        out_loss[0] = mean + 0.25f * mean;          // mean1 + BETA*mean2
    }
}

// ---------------------------------------------------------------------------
extern "C" void kernel_launch(void* const* d_in, const int* in_sizes, int n_in,
                              void* d_out, int out_size)
{
    const float* z = (const float*)d_in[0];   // (65536, 1, 256) fp32
    const float* e = (const float*)d_in[1];   // (1024, 256) fp32
    float* out = (float*)d_out;

    // Output layout: [z_q_st | indices | loss] flattened fp32 (tuple order).
    float* out_zq   = out;
    float* out_idx  = nullptr;
    float* out_loss = nullptr;
    long long total = (long long)out_size;
    const long long ZQ = (long long)NROWS * DIM;
    if (total >= ZQ + NROWS)     out_idx  = out + ZQ;
    if (total >= ZQ + NROWS + 1) out_loss = out + ZQ + NROWS;

    rowsumsq_z_kernel<<<NROWS / 8, 256>>>(z);
    rowsumsq_e_kernel<<<KCODES / 8, 256>>>(e);
    argmin_kernel<<<NROWS / BM, NTHREADS>>>(z, e);
    gather_kernel<<<NROWS / 8, 256>>>(z, e, out_zq, out_idx);
    if (out_loss) finalize_kernel<<<1, 256>>>(out_loss);
}

// round 6
// speedup vs baseline: 1.4191x; 1.4191x over previous
#include <cuda_runtime.h>
#include <cuda_bf16.h>

// Problem constants
#define NROWS    65536
#define DIM      256
#define KCODES   1024
#define CAND_CAP 24
#define MARGIN   2.0e-4f

// ---------------------------------------------------------------------------
// Device scratch (no allocations allowed; no host API calls anywhere in
// kernel_launch -- kernels reference these globals directly).
// ---------------------------------------------------------------------------
__device__ __align__(16) __nv_bfloat16 g_zh[NROWS * DIM];
__device__ __align__(16) __nv_bfloat16 g_zl[NROWS * DIM];
__device__ __align__(16) __nv_bfloat16 g_eh[KCODES * DIM];
__device__ __align__(16) __nv_bfloat16 g_el[KCODES * DIM];
__device__ float g_Sz[NROWS];
__device__ float g_Se[KCODES];
__device__ int   g_bestIdx[NROWS];
__device__ float g_partials[NROWS / 8];
__device__ int   g_cand[NROWS * CAND_CAP];
__device__ int   g_candCnt[NROWS];

// ---------------------------------------------------------------------------
// Warp MMA helpers (sm_80+ PTX: legal at -arch=sm_100)
// ---------------------------------------------------------------------------
__device__ __forceinline__ unsigned smem_u32(const void* p) {
    unsigned a;
    asm("{ .reg .u64 t; cvta.to.shared.u64 t, %1; cvt.u32.u64 %0, t; }"
        : "=r"(a) : "l"(p));
    return a;
}
#define LDSM_X4(d0, d1, d2, d3, addr)                                         \
    asm volatile("ldmatrix.sync.aligned.m8n8.x4.shared.b16 {%0,%1,%2,%3}, [%4];" \
                 : "=r"(d0), "=r"(d1), "=r"(d2), "=r"(d3) : "r"(addr))
#define MMA_BF16(c, a0, a1, a2, a3, b0, b1)                                   \
    asm volatile("mma.sync.aligned.m16n8k16.row.col.f32.bf16.bf16.f32 "       \
                 "{%0,%1,%2,%3}, {%4,%5,%6,%7}, {%8,%9}, {%0,%1,%2,%3};"      \
                 : "+f"((c)[0]), "+f"((c)[1]), "+f"((c)[2]), "+f"((c)[3])     \
                 : "r"(a0), "r"(a1), "r"(a2), "r"(a3), "r"(b0), "r"(b1))

// Order-preserving float -> uint key (ascending) for atomicMin-based row min.
__device__ __forceinline__ unsigned fkey(float f) {
    unsigned u = __float_as_uint(f);
    return (u & 0x80000000u) ? ~u : (u | 0x80000000u);
}
__device__ __forceinline__ float funkey(unsigned k) {
    unsigned u = (k & 0x80000000u) ? (k ^ 0x80000000u) : ~k;
    return __uint_as_float(u);
}

// ---------------------------------------------------------------------------
// Convert + row sum-of-squares. Sum-of-squares arithmetic is IDENTICAL to the
// R3 passing kernel (same mapping/expression/butterfly) -> g_Sz/g_Se bitexact.
// convert_z also zeroes per-row candidate counters (fresh every replay).
// ---------------------------------------------------------------------------
__device__ __forceinline__ unsigned pack_bf16x2(float a, float b) {
    __nv_bfloat16 ha = __float2bfloat16(a), hb = __float2bfloat16(b);
    return (unsigned)__bfloat16_as_ushort(ha) |
           ((unsigned)__bfloat16_as_ushort(hb) << 16);
}

__global__ void __launch_bounds__(256)
convert_z_kernel(const float* __restrict__ x)
{
    int warp = threadIdx.x >> 5;
    int lane = threadIdx.x & 31;
    int row  = blockIdx.x * 8 + warp;

    const float4* p = reinterpret_cast<const float4*>(x + (size_t)row * DIM);
    float s = 0.0f;
#pragma unroll
    for (int t = 0; t < 2; t++) {
        float4 v = p[lane + t * 32];
        s += v.x * v.x + v.y * v.y + v.z * v.z + v.w * v.w;

        float hx = __bfloat162float(__float2bfloat16(v.x));
        float hy = __bfloat162float(__float2bfloat16(v.y));
        float hz = __bfloat162float(__float2bfloat16(v.z));
        float hw = __bfloat162float(__float2bfloat16(v.w));
        uint2 hi, lo;
        hi.x = pack_bf16x2(v.x, v.y);
        hi.y = pack_bf16x2(v.z, v.w);
        lo.x = pack_bf16x2(v.x - hx, v.y - hy);
        lo.y = pack_bf16x2(v.z - hz, v.w - hw);
        size_t idx = (size_t)row * DIM + (size_t)(lane + t * 32) * 4;
        *reinterpret_cast<uint2*>(&g_zh[idx]) = hi;
        *reinterpret_cast<uint2*>(&g_zl[idx]) = lo;
    }
#pragma unroll
    for (int m = 16; m >= 1; m >>= 1)
        s += __shfl_xor_sync(0xffffffffu, s, m);
    if (lane == 0) {
        g_Sz[row] = s;
        g_candCnt[row] = 0;
    }
}

__global__ void __launch_bounds__(256)
convert_e_kernel(const float* __restrict__ x)
{
    int warp = threadIdx.x >> 5;
    int lane = threadIdx.x & 31;
    int row  = blockIdx.x * 8 + warp;

    const float4* p = reinterpret_cast<const float4*>(x + (size_t)row * DIM);
    float s = 0.0f;
#pragma unroll
    for (int t = 0; t < 2; t++) {
        float4 v = p[lane + t * 32];
        s += v.x * v.x + v.y * v.y + v.z * v.z + v.w * v.w;

        float hx = __bfloat162float(__float2bfloat16(v.x));
        float hy = __bfloat162float(__float2bfloat16(v.y));
        float hz = __bfloat162float(__float2bfloat16(v.z));
        float hw = __bfloat162float(__float2bfloat16(v.w));
        uint2 hi, lo;
        hi.x = pack_bf16x2(v.x, v.y);
        hi.y = pack_bf16x2(v.z, v.w);
        lo.x = pack_bf16x2(v.x - hx, v.y - hy);
        lo.y = pack_bf16x2(v.z - hz, v.w - hw);
        size_t idx = (size_t)row * DIM + (size_t)(lane + t * 32) * 4;
        *reinterpret_cast<uint2*>(&g_eh[idx]) = hi;
        *reinterpret_cast<uint2*>(&g_el[idx]) = lo;
    }
#pragma unroll
    for (int m = 16; m >= 1; m >>= 1)
        s += __shfl_xor_sync(0xffffffffu, s, m);
    if (lane == 0) g_Se[row] = s;
}

// ---------------------------------------------------------------------------
// Tensor-core candidate kernel (mma.sync bf16, hi/lo: zh*eh + zh*el + zl*eh).
// CTA = 128 rows x 1024 codes; chunks of N=128; k streamed in tiles of 32.
// STATIC shared only (45.5 KB < 48 KB): no cudaFuncSetAttribute needed.
// Per-row global prefix min kept in smem via atomicMin on ordered keys; each
// chunk: (1) fold this chunk's dists into row mins, (2) record codes within
// MARGIN of the row min into g_cand. True argmin provably always recorded
// (approx err ~2e-6 << MARGIN); overflow/empty -> exact full scan in refine.
// ---------------------------------------------------------------------------
#define A_STRIDE 80           // 32 bf16 = 64B data + 16B pad (conflict-free)
#define TILE_B   (128 * A_STRIDE)   // 10240

__global__ void __launch_bounds__(256, 2)
mma_cand_kernel()
{
    __shared__ float    ses[KCODES];             // 4096 B
    __shared__ unsigned rowMinK[128];            //  512 B
    __shared__ __align__(16) char sAh[TILE_B];   // 10240 B
    __shared__ __align__(16) char sAl[TILE_B];
    __shared__ __align__(16) char sBh[TILE_B];
    __shared__ __align__(16) char sBl[TILE_B];

    const int tid  = threadIdx.x;
    const int lane = tid & 31;
    const int wid  = tid >> 5;
    const int wm   = wid & 1;    // 64-row half
    const int wn   = wid >> 1;   // 32-col quarter of 128-chunk
    const int rowBase = blockIdx.x * 128;

#pragma unroll
    for (int t = 0; t < 4; t++)
        ses[tid + t * 256] = g_Se[tid + t * 256];
    if (tid < 128) rowMinK[tid] = 0xFFFFFFFFu;

    // ldmatrix base addresses
    const unsigned aB = smem_u32(sAh) +
        (unsigned)((wm * 64 + (lane & 15)) * A_STRIDE + (lane >> 4) * 16);
    const unsigned aOffL = smem_u32(sAl) - smem_u32(sAh);
    const unsigned bB = smem_u32(sBh) +
        (unsigned)((wn * 32 + ((lane >> 4) & 1) * 8 + (lane & 7)) * A_STRIDE +
                   ((lane >> 3) & 1) * 16);
    const unsigned bOffL = smem_u32(sBl) - smem_u32(sBh);

    for (int chunk = 0; chunk < 8; chunk++) {
        const int ct = chunk * 128;
        float acc[4][4][4];
#pragma unroll
        for (int mi = 0; mi < 4; mi++)
#pragma unroll
            for (int ni = 0; ni < 4; ni++)
#pragma unroll
                for (int q = 0; q < 4; q++)
                    acc[mi][ni][q] = 0.0f;

        for (int kt = 0; kt < 8; kt++) {
            // Load gmem -> regs (overlaps with other CTA / prior work)
            uint4 vAh[2], vAl[2], vBh[2], vBl[2];
#pragma unroll
            for (int it = 0; it < 2; it++) {
                int id = tid + it * 256;
                int r  = id >> 2;       // 0..127
                int c  = id & 3;        // 0..3 (16B units)
                size_t ga = (size_t)(rowBase + r) * DIM + kt * 32 + c * 8;
                size_t gb = (size_t)(ct + r) * DIM + kt * 32 + c * 8;
                vAh[it] = *reinterpret_cast<const uint4*>(g_zh + ga);
                vAl[it] = *reinterpret_cast<const uint4*>(g_zl + ga);
                vBh[it] = *reinterpret_cast<const uint4*>(g_eh + gb);
                vBl[it] = *reinterpret_cast<const uint4*>(g_el + gb);
            }
            __syncthreads();   // prior ldsm reads done before overwrite
#pragma unroll
            for (int it = 0; it < 2; it++) {
                int id = tid + it * 256;
                int r  = id >> 2;
                int c  = id & 3;
                int so = r * A_STRIDE + c * 16;
                *reinterpret_cast<uint4*>(sAh + so) = vAh[it];
                *reinterpret_cast<uint4*>(sAl + so) = vAl[it];
                *reinterpret_cast<uint4*>(sBh + so) = vBh[it];
                *reinterpret_cast<uint4*>(sBl + so) = vBl[it];
            }
            __syncthreads();

#pragma unroll
            for (int ks = 0; ks < 2; ks++) {
                unsigned be[2][4], bl[2][4];
#pragma unroll
                for (int np = 0; np < 2; np++) {
                    LDSM_X4(be[np][0], be[np][1], be[np][2], be[np][3],
                            bB + np * (16 * A_STRIDE) + ks * 32);
                    LDSM_X4(bl[np][0], bl[np][1], bl[np][2], bl[np][3],
                            bB + bOffL + np * (16 * A_STRIDE) + ks * 32);
                }
#pragma unroll
                for (int mi = 0; mi < 4; mi++) {
                    unsigned ah0, ah1, ah2, ah3, al0, al1, al2, al3;
                    LDSM_X4(ah0, ah1, ah2, ah3,
                            aB + mi * (16 * A_STRIDE) + ks * 32);
                    LDSM_X4(al0, al1, al2, al3,
                            aB + aOffL + mi * (16 * A_STRIDE) + ks * 32);
#pragma unroll
                    for (int ni = 0; ni < 4; ni++) {
                        int np = ni >> 1, o = (ni & 1) * 2;
                        MMA_BF16(acc[mi][ni], ah0, ah1, ah2, ah3,
                                 be[np][o], be[np][o + 1]);
                        MMA_BF16(acc[mi][ni], ah0, ah1, ah2, ah3,
                                 bl[np][o], bl[np][o + 1]);
                        MMA_BF16(acc[mi][ni], al0, al1, al2, al3,
                                 be[np][o], be[np][o + 1]);
                    }
                }
            }
        }

        // ---- Epilogue: dists in place, fold row mins, record candidates ----
        const int colb = wn * 32 + ((lane & 3) << 1);   // chunk-local column
#pragma unroll
        for (int mi = 0; mi < 4; mi++)
#pragma unroll
            for (int ni = 0; ni < 4; ni++) {
                float se0 = ses[ct + colb + ni * 8];
                float se1 = ses[ct + colb + ni * 8 + 1];
                acc[mi][ni][0] = fmaf(-2.0f, acc[mi][ni][0], se0);
                acc[mi][ni][1] = fmaf(-2.0f, acc[mi][ni][1], se1);
                acc[mi][ni][2] = fmaf(-2.0f, acc[mi][ni][2], se0);
                acc[mi][ni][3] = fmaf(-2.0f, acc[mi][ni][3], se1);
            }

        // Step 1: per-slot local min -> shared row min (ordered-uint atomicMin)
#pragma unroll
        for (int mi = 0; mi < 4; mi++)
#pragma unroll
            for (int h = 0; h < 2; h++) {
                float lm = 3.0e38f;
#pragma unroll
                for (int ni = 0; ni < 4; ni++) {
                    lm = fminf(lm, acc[mi][ni][h * 2]);
                    lm = fminf(lm, acc[mi][ni][h * 2 + 1]);
                }
                int lrow = wm * 64 + mi * 16 + h * 8 + (lane >> 2);
                atomicMin(&rowMinK[lrow], fkey(lm));
            }
        __syncthreads();

        // Step 2: record codes within MARGIN of row prefix min
#pragma unroll
        for (int mi = 0; mi < 4; mi++)
#pragma unroll
            for (int h = 0; h < 2; h++) {
                int   lrow = wm * 64 + mi * 16 + h * 8 + (lane >> 2);
                float th   = funkey(rowMinK[lrow]) + MARGIN;
                int   grow = rowBase + lrow;
#pragma unroll
                for (int ni = 0; ni < 4; ni++)
#pragma unroll
                    for (int j = 0; j < 2; j++) {
                        float d = acc[mi][ni][h * 2 + j];
                        if (d < th) {
                            int s = atomicAdd(&g_candCnt[grow], 1);
                            if (s < CAND_CAP)
                                g_cand[grow * CAND_CAP + s] =
                                    ct + colb + ni * 8 + j;
                        }
                    }
            }
        // next chunk's fill begins with __syncthreads(): rowMinK reads safe
    }
}

// ---------------------------------------------------------------------------
// Exact refinement: replicates R3's arithmetic bit-for-bit (sequential
// ascending-k fmaf dot, dist = fmaf(-2, dot, fl(Sz+Se)), lex (dist,idx) min).
// One warp per row. m==1 -> the single recorded candidate IS the winner.
// m==0 or m>CAND_CAP -> exact full scan (safety / overflow path).
// ---------------------------------------------------------------------------
__global__ void __launch_bounds__(256)
refine_kernel(const float* __restrict__ z, const float* __restrict__ e)
{
    int warp = threadIdx.x >> 5;
    int lane = threadIdx.x & 31;
    int row  = blockIdx.x * 8 + warp;

    int m = g_candCnt[row];
    if (m == 1) {
        if (lane == 0) g_bestIdx[row] = g_cand[(size_t)row * CAND_CAP];
        return;
    }

    float sz = g_Sz[row];
    const float* zr = z + (size_t)row * DIM;
    float bd = 3.0e38f;
    int   bc = 0x7FFFFFFF;

    if (m >= 2 && m <= CAND_CAP) {           // fast path: candidates only
        if (lane < m) {
            int code = g_cand[(size_t)row * CAND_CAP + lane];
            const float* er = e + (size_t)code * DIM;
            float acc = 0.0f;
#pragma unroll 8
            for (int k = 0; k < DIM; k++)
                acc = fmaf(zr[k], er[k], acc);
            float t = sz + g_Se[code];
            bd = fmaf(-2.0f, acc, t);
            bc = code;
        }
    } else {                                 // overflow / safety: scan all
        for (int code = lane; code < KCODES; code += 32) {
            const float* er = e + (size_t)code * DIM;
            float acc = 0.0f;
#pragma unroll 8
            for (int k = 0; k < DIM; k++)
                acc = fmaf(zr[k], er[k], acc);
            float t    = sz + g_Se[code];
            float dist = fmaf(-2.0f, acc, t);
            if (dist < bd || (dist == bd && code < bc)) { bd = dist; bc = code; }
        }
    }

#pragma unroll
    for (int s = 16; s >= 1; s >>= 1) {
        float od = __shfl_xor_sync(0xffffffffu, bd, s);
        int   oc = __shfl_xor_sync(0xffffffffu, bc, s);
        if (od < bd || (od == bd && oc < bc)) { bd = od; bc = oc; }
    }
    if (lane == 0) g_bestIdx[row] = bc;
}

// ---------------------------------------------------------------------------
// Gather + loss partials (unchanged from R3)
// ---------------------------------------------------------------------------
__global__ void __launch_bounds__(256)
gather_kernel(const float* __restrict__ z, const float* __restrict__ e,
              float* __restrict__ out_zq, float* __restrict__ out_idx)
{
    __shared__ float ws[8];
    int warp = threadIdx.x >> 5;
    int lane = threadIdx.x & 31;
    int row  = blockIdx.x * 8 + warp;

    int idx = g_bestIdx[row];
    const float4* zp = reinterpret_cast<const float4*>(z + (size_t)row * DIM);
    const float4* qp = reinterpret_cast<const float4*>(e + (size_t)idx * DIM);
    float4*       op = reinterpret_cast<float4*>(out_zq + (size_t)row * DIM);

    float local = 0.0f;
#pragma unroll
    for (int t = 0; t < 2; t++) {
        int c = lane + t * 32;
        float4 zv = zp[c];
        float4 qv = qp[c];
        float dx = qv.x - zv.x, dy = qv.y - zv.y;
        float dz2 = qv.z - zv.z, dw = qv.w - zv.w;
        float4 o = make_float4(zv.x + dx, zv.y + dy, zv.z + dz2, zv.w + dw);
        op[c] = o;
        local += dx * dx + dy * dy + dz2 * dz2 + dw * dw;
    }
#pragma unroll
    for (int s = 16; s >= 1; s >>= 1)
        local += __shfl_xor_sync(0xffffffffu, local, s);

    if (lane == 0) {
        ws[warp] = local;
        if (out_idx) out_idx[row] = (float)idx;
    }
    __syncthreads();
    if (threadIdx.x == 0) {
        float s = 0.0f;
#pragma unroll
        for (int w = 0; w < 8; w++) s += ws[w];
        g_partials[blockIdx.x] = s;
    }
}

__global__ void __launch_bounds__(256)
finalize_kernel(float* __restrict__ out_loss)
{
    __shared__ float sm[256];
    float s = 0.0f;
    for (int i = threadIdx.x; i < NROWS / 8; i += 256)
        s += g_partials[i];
    sm[threadIdx.x] = s;
    __syncthreads();
    for (int m = 128; m >= 1; m >>= 1) {
        if (threadIdx.x < m) sm[threadIdx.x] += sm[threadIdx.x + m];
        __syncthreads();
    }
    if (threadIdx.x == 0) {
        float mean = sm[0] / 16777216.0f;
        out_loss[0] = mean + 0.25f * mean;
    }
}

// ---------------------------------------------------------------------------
// kernel_launch: ONLY kernel launches (no other runtime API calls).
// ---------------------------------------------------------------------------
extern "C" void kernel_launch(void* const* d_in, const int* in_sizes, int n_in,
                              void* d_out, int out_size)
{
    const float* z = (const float*)d_in[0];   // (65536, 1, 256) fp32
    const float* e = (const float*)d_in[1];   // (1024, 256) fp32
    float* out = (float*)d_out;

    float* out_zq   = out;
    float* out_idx  = nullptr;
    float* out_loss = nullptr;
    long long total = (long long)out_size;
    const long long ZQ = (long long)NROWS * DIM;
    if (total >= ZQ + NROWS)     out_idx  = out + ZQ;
    if (total >= ZQ + NROWS + 1) out_loss = out + ZQ + NROWS;

    convert_z_kernel<<<NROWS / 8, 256>>>(z);
    convert_e_kernel<<<KCODES / 8, 256>>>(e);
    mma_cand_kernel<<<NROWS / 128, 256>>>();
    refine_kernel<<<NROWS / 8, 256>>>(z, e);
    gather_kernel<<<NROWS / 8, 256>>>(z, e, out_zq, out_idx);
    if (out_loss) finalize_kernel<<<1, 256>>>(out_loss);
}

// round 8
// speedup vs baseline: 3.6083x; 2.5426x over previous
#include <cuda_runtime.h>
#include <cuda_bf16.h>

// Problem constants
#define NROWS    65536
#define DIM      256
#define KCODES   1024
#define CAND_CAP 24
#define MARGIN   1.0e-3f

// ---------------------------------------------------------------------------
// Device scratch (no allocations; kernel_launch does ONLY kernel launches)
// ---------------------------------------------------------------------------
__device__ __align__(16) __nv_bfloat16 g_zh[NROWS * DIM];
__device__ __align__(16) __nv_bfloat16 g_eh[KCODES * DIM];
__device__ float g_Sz[NROWS];
__device__ float g_Se[KCODES];
__device__ float g_rowMin[NROWS];
__device__ int   g_bestIdx[NROWS];
__device__ float g_partials[NROWS / 8];
__device__ int   g_cand[NROWS * CAND_CAP];
__device__ float g_candDist[NROWS * CAND_CAP];
__device__ int   g_candCnt[NROWS];

// ---------------------------------------------------------------------------
// Warp MMA helpers (sm_80+ PTX: legal at -arch=sm_100)
// ---------------------------------------------------------------------------
__device__ __forceinline__ unsigned smem_u32(const void* p) {
    unsigned a;
    asm("{ .reg .u64 t; cvta.to.shared.u64 t, %1; cvt.u32.u64 %0, t; }"
        : "=r"(a) : "l"(p));
    return a;
}
#define LDSM_X4(d0, d1, d2, d3, addr)                                         \
    asm volatile("ldmatrix.sync.aligned.m8n8.x4.shared.b16 {%0,%1,%2,%3}, [%4];" \
                 : "=r"(d0), "=r"(d1), "=r"(d2), "=r"(d3) : "r"(addr))
#define MMA_BF16(c, a0, a1, a2, a3, b0, b1)                                   \
    asm volatile("mma.sync.aligned.m16n8k16.row.col.f32.bf16.bf16.f32 "       \
                 "{%0,%1,%2,%3}, {%4,%5,%6,%7}, {%8,%9}, {%0,%1,%2,%3};"      \
                 : "+f"((c)[0]), "+f"((c)[1]), "+f"((c)[2]), "+f"((c)[3])     \
                 : "r"(a0), "r"(a1), "r"(a2), "r"(a3), "r"(b0), "r"(b1))

// Order-preserving float <-> uint key (ascending) for atomicMin row mins.
__device__ __forceinline__ unsigned fkey(float f) {
    unsigned u = __float_as_uint(f);
    return (u & 0x80000000u) ? ~u : (u | 0x80000000u);
}
__device__ __forceinline__ float funkey(unsigned k) {
    unsigned u = (k & 0x80000000u) ? (k ^ 0x80000000u) : ~k;
    return __uint_as_float(u);
}

// ---------------------------------------------------------------------------
// Convert to bf16 + row sum-of-squares (Sz/Se arithmetic identical to the
// R3/R6 passing kernels). convert_z also zeroes candidate counters per replay.
// ---------------------------------------------------------------------------
__device__ __forceinline__ unsigned pack_bf16x2(float a, float b) {
    __nv_bfloat16 ha = __float2bfloat16(a), hb = __float2bfloat16(b);
    return (unsigned)__bfloat16_as_ushort(ha) |
           ((unsigned)__bfloat16_as_ushort(hb) << 16);
}

__global__ void __launch_bounds__(256)
convert_z_kernel(const float* __restrict__ x)
{
    int warp = threadIdx.x >> 5;
    int lane = threadIdx.x & 31;
    int row  = blockIdx.x * 8 + warp;

    const float4* p = reinterpret_cast<const float4*>(x + (size_t)row * DIM);
    float s = 0.0f;
#pragma unroll
    for (int t = 0; t < 2; t++) {
        float4 v = p[lane + t * 32];
        s += v.x * v.x + v.y * v.y + v.z * v.z + v.w * v.w;
        uint2 hi;
        hi.x = pack_bf16x2(v.x, v.y);
        hi.y = pack_bf16x2(v.z, v.w);
        *reinterpret_cast<uint2*>(
            &g_zh[(size_t)row * DIM + (size_t)(lane + t * 32) * 4]) = hi;
    }
#pragma unroll
    for (int m = 16; m >= 1; m >>= 1)
        s += __shfl_xor_sync(0xffffffffu, s, m);
    if (lane == 0) {
        g_Sz[row] = s;
        g_candCnt[row] = 0;
    }
}

__global__ void __launch_bounds__(256)
convert_e_kernel(const float* __restrict__ x)
{
    int warp = threadIdx.x >> 5;
    int lane = threadIdx.x & 31;
    int row  = blockIdx.x * 8 + warp;

    const float4* p = reinterpret_cast<const float4*>(x + (size_t)row * DIM);
    float s = 0.0f;
#pragma unroll
    for (int t = 0; t < 2; t++) {
        float4 v = p[lane + t * 32];
        s += v.x * v.x + v.y * v.y + v.z * v.z + v.w * v.w;
        uint2 hi;
        hi.x = pack_bf16x2(v.x, v.y);
        hi.y = pack_bf16x2(v.z, v.w);
        *reinterpret_cast<uint2*>(
            &g_eh[(size_t)row * DIM + (size_t)(lane + t * 32) * 4]) = hi;
    }
#pragma unroll
    for (int m = 16; m >= 1; m >>= 1)
        s += __shfl_xor_sync(0xffffffffu, s, m);
    if (lane == 0) g_Se[row] = s;
}

// ---------------------------------------------------------------------------
// Tensor-core candidate kernel, single bf16 pass (zh*eh), double-buffered.
// CTA = 128 rows x 1024 codes; 8 chunks of N=128; k in tiles of 32.
// R7 bug fixed: tile loads now cover ALL 128 rows (2 uint4/thread/array).
// Static shared only (~45.5 KB). Per-row prefix min via atomicMin on ordered
// keys; codes within MARGIN of the prefix min recorded with approx dist;
// refine filters against the FINAL row min (g_rowMin).
// Winner always captured: d_hat(w) - d_hat_min <= 2*err (~2e-4 worst) << MARGIN.
// ---------------------------------------------------------------------------
#define A_STRIDE 80                 // 32 bf16 = 64B + 16B pad (conflict-free)
#define TILE_B   (128 * A_STRIDE)   // 10240 B

__global__ void __launch_bounds__(256, 2)
mma_cand_kernel()
{
    __shared__ float    ses[KCODES];                 // 4096 B
    __shared__ unsigned rowMinK[128];                //  512 B
    __shared__ __align__(16) char sA[2 * TILE_B];    // 20480 B
    __shared__ __align__(16) char sB[2 * TILE_B];    // 20480 B

    const int tid  = threadIdx.x;
    const int lane = tid & 31;
    const int wid  = tid >> 5;
    const int wm   = wid & 1;    // 64-row half
    const int wn   = wid >> 1;   // 32-col quarter of the 128-chunk
    const int rowBase = blockIdx.x * 128;

#pragma unroll
    for (int t = 0; t < 4; t++)
        ses[tid + t * 256] = g_Se[tid + t * 256];
    if (tid < 128) rowMinK[tid] = 0xFFFFFFFFu;

    const unsigned aB = smem_u32(sA) +
        (unsigned)((wm * 64 + (lane & 15)) * A_STRIDE + (lane >> 4) * 16);
    const unsigned bB = smem_u32(sB) +
        (unsigned)((wn * 32 + ((lane >> 4) & 1) * 8 + (lane & 7)) * A_STRIDE +
                   ((lane >> 3) & 1) * 16);

    for (int chunk = 0; chunk < 8; chunk++) {
        const int ct = chunk * 128;
        float acc[4][4][4];
#pragma unroll
        for (int mi = 0; mi < 4; mi++)
#pragma unroll
            for (int ni = 0; ni < 4; ni++)
#pragma unroll
                for (int q = 0; q < 4; q++)
                    acc[mi][ni][q] = 0.0f;

        // Preload k-tile 0 into buffer 0 (readers of buf0 are behind the
        // previous chunk's epilogue barriers). 2 uint4/thread/array: ALL rows.
#pragma unroll
        for (int it = 0; it < 2; it++) {
            int id = tid + it * 256;       // 0..511
            int r  = id >> 2;              // 0..127
            int c  = id & 3;               // 0..3 (16B units)
            int so = r * A_STRIDE + c * 16;
            *reinterpret_cast<uint4*>(sA + so) =
                *reinterpret_cast<const uint4*>(
                    g_zh + (size_t)(rowBase + r) * DIM + c * 8);
            *reinterpret_cast<uint4*>(sB + so) =
                *reinterpret_cast<const uint4*>(
                    g_eh + (size_t)(ct + r) * DIM + c * 8);
        }
        __syncthreads();

        for (int kt = 0; kt < 8; kt++) {
            // Prefetch next k-tile while computing this one
            uint4 va[2], vb[2];
            if (kt < 7) {
#pragma unroll
                for (int it = 0; it < 2; it++) {
                    int id = tid + it * 256;
                    int r  = id >> 2;
                    int c  = id & 3;
                    va[it] = *reinterpret_cast<const uint4*>(
                        g_zh + (size_t)(rowBase + r) * DIM + (kt + 1) * 32 + c * 8);
                    vb[it] = *reinterpret_cast<const uint4*>(
                        g_eh + (size_t)(ct + r) * DIM + (kt + 1) * 32 + c * 8);
                }
            }

            const unsigned bo = (unsigned)((kt & 1) * TILE_B);
#pragma unroll
            for (int ks = 0; ks < 2; ks++) {
                unsigned b0[4], b1[4];
                LDSM_X4(b0[0], b0[1], b0[2], b0[3],
                        bB + bo + 0 * (16 * A_STRIDE) + ks * 32);
                LDSM_X4(b1[0], b1[1], b1[2], b1[3],
                        bB + bo + 1 * (16 * A_STRIDE) + ks * 32);
#pragma unroll
                for (int mi = 0; mi < 4; mi++) {
                    unsigned a0, a1, a2, a3;
                    LDSM_X4(a0, a1, a2, a3,
                            aB + bo + mi * (16 * A_STRIDE) + ks * 32);
                    MMA_BF16(acc[mi][0], a0, a1, a2, a3, b0[0], b0[1]);
                    MMA_BF16(acc[mi][1], a0, a1, a2, a3, b0[2], b0[3]);
                    MMA_BF16(acc[mi][2], a0, a1, a2, a3, b1[0], b1[1]);
                    MMA_BF16(acc[mi][3], a0, a1, a2, a3, b1[2], b1[3]);
                }
            }

            if (kt < 7) {
                // Write buffer (kt+1)&1: its prior readers (compute of kt-1)
                // are behind the barrier at the end of iteration kt-1.
#pragma unroll
                for (int it = 0; it < 2; it++) {
                    int id = tid + it * 256;
                    int r  = id >> 2;
                    int c  = id & 3;
                    int sd = ((kt + 1) & 1) * TILE_B + r * A_STRIDE + c * 16;
                    *reinterpret_cast<uint4*>(sA + sd) = va[it];
                    *reinterpret_cast<uint4*>(sB + sd) = vb[it];
                }
                __syncthreads();
            }
        }

        // ---- Epilogue: dist = Se - 2*dot (Sz row-constant, dropped) ----
        const int colb = wn * 32 + ((lane & 3) << 1);   // chunk-local column
#pragma unroll
        for (int mi = 0; mi < 4; mi++)
#pragma unroll
            for (int ni = 0; ni < 4; ni++) {
                float se0 = ses[ct + colb + ni * 8];
                float se1 = ses[ct + colb + ni * 8 + 1];
                acc[mi][ni][0] = fmaf(-2.0f, acc[mi][ni][0], se0);
                acc[mi][ni][1] = fmaf(-2.0f, acc[mi][ni][1], se1);
                acc[mi][ni][2] = fmaf(-2.0f, acc[mi][ni][2], se0);
                acc[mi][ni][3] = fmaf(-2.0f, acc[mi][ni][3], se1);
            }

        // Step 1: fold this chunk into the shared per-row prefix min
#pragma unroll
        for (int mi = 0; mi < 4; mi++)
#pragma unroll
            for (int h = 0; h < 2; h++) {
                float lm = 3.0e38f;
#pragma unroll
                for (int ni = 0; ni < 4; ni++) {
                    lm = fminf(lm, acc[mi][ni][h * 2]);
                    lm = fminf(lm, acc[mi][ni][h * 2 + 1]);
                }
                atomicMin(&rowMinK[wm * 64 + mi * 16 + h * 8 + (lane >> 2)],
                          fkey(lm));
            }
        __syncthreads();

        // Step 2: record codes within MARGIN of the prefix min (+ dist)
#pragma unroll
        for (int mi = 0; mi < 4; mi++)
#pragma unroll
            for (int h = 0; h < 2; h++) {
                int   lrow = wm * 64 + mi * 16 + h * 8 + (lane >> 2);
                float th   = funkey(rowMinK[lrow]) + MARGIN;
                int   grow = rowBase + lrow;
#pragma unroll
                for (int ni = 0; ni < 4; ni++)
#pragma unroll
                    for (int j = 0; j < 2; j++) {
                        float d = acc[mi][ni][h * 2 + j];
                        if (d < th) {
                            int s = atomicAdd(&g_candCnt[grow], 1);
                            if (s < CAND_CAP) {
                                g_cand[grow * CAND_CAP + s] =
                                    ct + colb + ni * 8 + j;
                                g_candDist[grow * CAND_CAP + s] = d;
                            }
                        }
                    }
            }
        __syncthreads();
    }

    // Publish final per-row approx min for the refine filter
    if (tid < 128) g_rowMin[rowBase + tid] = funkey(rowMinK[tid]);
}

// ---------------------------------------------------------------------------
// Refine: filter candidates against the FINAL approx row min. One survivor ->
// winner directly. Multiple -> warp-cooperative exact fp32 dots (error ~1e-7,
// far below the ulp(256)~3e-5 grid the reference's distances quantize to;
// same final ops: t = fl(Sz+Se), dist = fmaf(-2, dot, t); lex (dist,idx) min).
// Empty survivor set (impossible by construction) or overflow -> full exact
// scan. bc always initialized to a VALID code: gather can never wild-read.
// ---------------------------------------------------------------------------
__global__ void __launch_bounds__(256)
refine_kernel(const float* __restrict__ z, const float* __restrict__ e)
{
    int warp = threadIdx.x >> 5;
    int lane = threadIdx.x & 31;
    int row  = blockIdx.x * 8 + warp;

    int  m = g_candCnt[row];
    bool fullscan = (m > CAND_CAP);
    float bd = 3.0e38f;
    int   bc = 0;                       // valid fallback code

    if (!fullscan) {
        float th   = g_rowMin[row] + MARGIN;
        int   code = 0;
        bool  eff  = false;
        if (lane < m) {
            code = g_cand[(size_t)row * CAND_CAP + lane];
            eff  = g_candDist[(size_t)row * CAND_CAP + lane] < th;
        }
        unsigned mask = __ballot_sync(0xffffffffu, eff);
        int pc = __popc(mask);
        if (pc == 1) {
            if (lane == (__ffs(mask) - 1)) g_bestIdx[row] = code;
            return;
        }
        if (pc == 0) {
            fullscan = true;            // defensive: degrade, never garbage
        } else {
            // Warp-cooperative exact dots over the few survivors.
            float sz = g_Sz[row];
            const float4* zp =
                reinterpret_cast<const float4*>(z + (size_t)row * DIM);
            float4 z0 = zp[lane * 2];
            float4 z1 = zp[lane * 2 + 1];
            for (unsigned mm = mask; mm; mm &= (mm - 1)) {
                int i = __ffs(mm) - 1;
                int c = __shfl_sync(0xffffffffu, code, i);
                const float4* ep =
                    reinterpret_cast<const float4*>(e + (size_t)c * DIM);
                float4 e0 = ep[lane * 2];
                float4 e1 = ep[lane * 2 + 1];
                float acc = 0.0f;
                acc = fmaf(z0.x, e0.x, acc); acc = fmaf(z0.y, e0.y, acc);
                acc = fmaf(z0.z, e0.z, acc); acc = fmaf(z0.w, e0.w, acc);
                acc = fmaf(z1.x, e1.x, acc); acc = fmaf(z1.y, e1.y, acc);
                acc = fmaf(z1.z, e1.z, acc); acc = fmaf(z1.w, e1.w, acc);
#pragma unroll
                for (int s = 16; s >= 1; s >>= 1)
                    acc += __shfl_xor_sync(0xffffffffu, acc, s);
                float t    = sz + g_Se[c];
                float dist = fmaf(-2.0f, acc, t);
                if (dist < bd || (dist == bd && c < bc)) { bd = dist; bc = c; }
            }
            if (lane == 0) g_bestIdx[row] = bc;   // all lanes agree
            return;
        }
    }

    // Full exact scan (overflow / defensive path)
    {
        float sz = g_Sz[row];
        const float* zr = z + (size_t)row * DIM;
        bd = 3.0e38f;
        bc = 0;
        for (int c = lane; c < KCODES; c += 32) {
            const float* er = e + (size_t)c * DIM;
            float acc = 0.0f;
#pragma unroll 8
            for (int k = 0; k < DIM; k++)
                acc = fmaf(zr[k], er[k], acc);
            float t    = sz + g_Se[c];
            float dist = fmaf(-2.0f, acc, t);
            if (dist < bd || (dist == bd && c < bc)) { bd = dist; bc = c; }
        }
#pragma unroll
        for (int s = 16; s >= 1; s >>= 1) {
            float od = __shfl_xor_sync(0xffffffffu, bd, s);
            int   oc = __shfl_xor_sync(0xffffffffu, bc, s);
            if (od < bd || (od == bd && oc < bc)) { bd = od; bc = oc; }
        }
        if (lane == 0) g_bestIdx[row] = bc;
    }
}

// ---------------------------------------------------------------------------
// Gather + loss partials (unchanged from R3/R6)
// ---------------------------------------------------------------------------
__global__ void __launch_bounds__(256)
gather_kernel(const float* __restrict__ z, const float* __restrict__ e,
              float* __restrict__ out_zq, float* __restrict__ out_idx)
{
    __shared__ float ws[8];
    int warp = threadIdx.x >> 5;
    int lane = threadIdx.x & 31;
    int row  = blockIdx.x * 8 + warp;

    int idx = g_bestIdx[row];
    const float4* zp = reinterpret_cast<const float4*>(z + (size_t)row * DIM);
    const float4* qp = reinterpret_cast<const float4*>(e + (size_t)idx * DIM);
    float4*       op = reinterpret_cast<float4*>(out_zq + (size_t)row * DIM);

    float local = 0.0f;
#pragma unroll
    for (int t = 0; t < 2; t++) {
        int c = lane + t * 32;
        float4 zv = zp[c];
        float4 qv = qp[c];
        float dx = qv.x - zv.x, dy = qv.y - zv.y;
        float dz2 = qv.z - zv.z, dw = qv.w - zv.w;
        float4 o = make_float4(zv.x + dx, zv.y + dy, zv.z + dz2, zv.w + dw);
        op[c] = o;
        local += dx * dx + dy * dy + dz2 * dz2 + dw * dw;
    }
#pragma unroll
    for (int s = 16; s >= 1; s >>= 1)
        local += __shfl_xor_sync(0xffffffffu, local, s);

    if (lane == 0) {
        ws[warp] = local;
        if (out_idx) out_idx[row] = (float)idx;
    }
    __syncthreads();
    if (threadIdx.x == 0) {
        float s = 0.0f;
#pragma unroll
        for (int w = 0; w < 8; w++) s += ws[w];
        g_partials[blockIdx.x] = s;
    }
}

__global__ void __launch_bounds__(256)
finalize_kernel(float* __restrict__ out_loss)
{
    __shared__ float sm[256];
    float s = 0.0f;
    for (int i = threadIdx.x; i < NROWS / 8; i += 256)
        s += g_partials[i];
    sm[threadIdx.x] = s;
    __syncthreads();
    for (int m = 128; m >= 1; m >>= 1) {
        if (threadIdx.x < m) sm[threadIdx.x] += sm[threadIdx.x + m];
        __syncthreads();
    }
    if (threadIdx.x == 0) {
        float mean = sm[0] / 16777216.0f;
        out_loss[0] = mean + 0.25f * mean;
    }
}

// ---------------------------------------------------------------------------
// kernel_launch: ONLY kernel launches (no other runtime API calls).
// ---------------------------------------------------------------------------
extern "C" void kernel_launch(void* const* d_in, const int* in_sizes, int n_in,
                              void* d_out, int out_size)
{
    const float* z = (const float*)d_in[0];   // (65536, 1, 256) fp32
    const float* e = (const float*)d_in[1];   // (1024, 256) fp32
    float* out = (float*)d_out;

    float* out_zq   = out;
    float* out_idx  = nullptr;
    float* out_loss = nullptr;
    long long total = (long long)out_size;
    const long long ZQ = (long long)NROWS * DIM;
    if (total >= ZQ + NROWS)     out_idx  = out + ZQ;
    if (total >= ZQ + NROWS + 1) out_loss = out + ZQ + NROWS;

    convert_z_kernel<<<NROWS / 8, 256>>>(z);
    convert_e_kernel<<<KCODES / 8, 256>>>(e);
    mma_cand_kernel<<<NROWS / 128, 256>>>();
    refine_kernel<<<NROWS / 8, 256>>>(z, e);
    gather_kernel<<<NROWS / 8, 256>>>(z, e, out_zq, out_idx);
    if (out_loss) finalize_kernel<<<1, 256>>>(out_loss);
}

// round 9
// speedup vs baseline: 4.0480x; 1.1219x over previous
#include <cuda_runtime.h>
#include <cuda_bf16.h>

// Problem constants
#define NROWS    65536
#define DIM      256
#define KCODES   1024
#define CAND_CAP 24
#define MARGIN   1.0e-3f

// ---------------------------------------------------------------------------
// Device scratch (no allocations; kernel_launch does ONLY kernel launches)
// ---------------------------------------------------------------------------
__device__ __align__(16) __nv_bfloat16 g_zh[NROWS * DIM];
__device__ __align__(16) __nv_bfloat16 g_eh[KCODES * DIM];
__device__ float g_Sz[NROWS];
__device__ float g_Se[KCODES];
__device__ float g_rowMin[NROWS];
__device__ float g_partials[NROWS / 8];
__device__ int   g_cand[NROWS * CAND_CAP];
__device__ float g_candDist[NROWS * CAND_CAP];
__device__ int   g_candCnt[NROWS];

// ---------------------------------------------------------------------------
// PTX helpers (sm_80+ features only: legal at -arch=sm_100)
// ---------------------------------------------------------------------------
__device__ __forceinline__ unsigned smem_u32(const void* p) {
    unsigned a;
    asm("{ .reg .u64 t; cvta.to.shared.u64 t, %1; cvt.u32.u64 %0, t; }"
        : "=r"(a) : "l"(p));
    return a;
}
#define LDSM_X4(d0, d1, d2, d3, addr)                                         \
    asm volatile("ldmatrix.sync.aligned.m8n8.x4.shared.b16 {%0,%1,%2,%3}, [%4];" \
                 : "=r"(d0), "=r"(d1), "=r"(d2), "=r"(d3) : "r"(addr))
#define MMA_BF16(c, a0, a1, a2, a3, b0, b1)                                   \
    asm volatile("mma.sync.aligned.m16n8k16.row.col.f32.bf16.bf16.f32 "       \
                 "{%0,%1,%2,%3}, {%4,%5,%6,%7}, {%8,%9}, {%0,%1,%2,%3};"      \
                 : "+f"((c)[0]), "+f"((c)[1]), "+f"((c)[2]), "+f"((c)[3])     \
                 : "r"(a0), "r"(a1), "r"(a2), "r"(a3), "r"(b0), "r"(b1))
#define CP_ASYNC16(dst, src)                                                  \
    asm volatile("cp.async.cg.shared.global [%0], [%1], 16;"                  \
                 :: "r"(dst), "l"(src))
#define CP_COMMIT() asm volatile("cp.async.commit_group;")
#define CP_WAIT0()  asm volatile("cp.async.wait_group 0;")

// Order-preserving float <-> uint key (ascending) for atomicMin row mins.
__device__ __forceinline__ unsigned fkey(float f) {
    unsigned u = __float_as_uint(f);
    return (u & 0x80000000u) ? ~u : (u | 0x80000000u);
}
__device__ __forceinline__ float funkey(unsigned k) {
    unsigned u = (k & 0x80000000u) ? (k ^ 0x80000000u) : ~k;
    return __uint_as_float(u);
}

// ---------------------------------------------------------------------------
// Convert to bf16 + row sum-of-squares (Sz/Se arithmetic identical to R3/R8).
// convert_z also zeroes candidate counters (fresh every graph replay).
// ---------------------------------------------------------------------------
__device__ __forceinline__ unsigned pack_bf16x2(float a, float b) {
    __nv_bfloat16 ha = __float2bfloat16(a), hb = __float2bfloat16(b);
    return (unsigned)__bfloat16_as_ushort(ha) |
           ((unsigned)__bfloat16_as_ushort(hb) << 16);
}

__global__ void __launch_bounds__(256)
convert_z_kernel(const float* __restrict__ x)
{
    int warp = threadIdx.x >> 5;
    int lane = threadIdx.x & 31;
    int row  = blockIdx.x * 8 + warp;

    const float4* p = reinterpret_cast<const float4*>(x + (size_t)row * DIM);
    float s = 0.0f;
#pragma unroll
    for (int t = 0; t < 2; t++) {
        float4 v = p[lane + t * 32];
        s += v.x * v.x + v.y * v.y + v.z * v.z + v.w * v.w;
        uint2 hi;
        hi.x = pack_bf16x2(v.x, v.y);
        hi.y = pack_bf16x2(v.z, v.w);
        *reinterpret_cast<uint2*>(
            &g_zh[(size_t)row * DIM + (size_t)(lane + t * 32) * 4]) = hi;
    }
#pragma unroll
    for (int m = 16; m >= 1; m >>= 1)
        s += __shfl_xor_sync(0xffffffffu, s, m);
    if (lane == 0) {
        g_Sz[row] = s;
        g_candCnt[row] = 0;
    }
}

__global__ void __launch_bounds__(256)
convert_e_kernel(const float* __restrict__ x)
{
    int warp = threadIdx.x >> 5;
    int lane = threadIdx.x & 31;
    int row  = blockIdx.x * 8 + warp;

    const float4* p = reinterpret_cast<const float4*>(x + (size_t)row * DIM);
    float s = 0.0f;
#pragma unroll
    for (int t = 0; t < 2; t++) {
        float4 v = p[lane + t * 32];
        s += v.x * v.x + v.y * v.y + v.z * v.z + v.w * v.w;
        uint2 hi;
        hi.x = pack_bf16x2(v.x, v.y);
        hi.y = pack_bf16x2(v.z, v.w);
        *reinterpret_cast<uint2*>(
            &g_eh[(size_t)row * DIM + (size_t)(lane + t * 32) * 4]) = hi;
    }
#pragma unroll
    for (int m = 16; m >= 1; m >>= 1)
        s += __shfl_xor_sync(0xffffffffu, s, m);
    if (lane == 0) g_Se[row] = s;
}

// ---------------------------------------------------------------------------
// Tensor-core candidate kernel, single bf16 pass (zh*eh), cp.async
// double-buffered k pipeline. CTA = 128 rows x 1024 codes; 8 chunks of N=128.
// Epilogue: quad-shfl row min + ONE shared atomicMin per row per warp (32x
// fewer ATOMS than R8), then margin-candidate recording (no trailing sync --
// rowMinK is monotonic; stale thresholds are conservative).
// Winner always captured: d_hat(w) - d_hat_min <= 2*err (~2e-4 worst) << MARGIN.
// ---------------------------------------------------------------------------
#define A_STRIDE 80                 // 32 bf16 = 64B + 16B pad (conflict-free)
#define TILE_B   (128 * A_STRIDE)   // 10240 B

__global__ void __launch_bounds__(256, 2)
mma_cand_kernel()
{
    __shared__ float    ses[KCODES];                 //  4096 B
    __shared__ unsigned rowMinK[128];                //   512 B
    __shared__ __align__(16) char sA[2 * TILE_B];    // 20480 B
    __shared__ __align__(16) char sB[2 * TILE_B];    // 20480 B

    const int tid  = threadIdx.x;
    const int lane = tid & 31;
    const int wid  = tid >> 5;
    const int wm   = wid & 1;    // 64-row half
    const int wn   = wid >> 1;   // 32-col quarter of the 128-chunk
    const int rowBase = blockIdx.x * 128;

#pragma unroll
    for (int t = 0; t < 4; t++)
        ses[tid + t * 256] = g_Se[tid + t * 256];
    if (tid < 128) rowMinK[tid] = 0xFFFFFFFFu;

    // ldmatrix read addresses
    const unsigned aB = smem_u32(sA) +
        (unsigned)((wm * 64 + (lane & 15)) * A_STRIDE + (lane >> 4) * 16);
    const unsigned bB = smem_u32(sB) +
        (unsigned)((wn * 32 + ((lane >> 4) & 1) * 8 + (lane & 7)) * A_STRIDE +
                   ((lane >> 3) & 1) * 16);

    // cp.async per-thread addressing: two rows (r0, r0+64), 16B column c
    const int r0 = tid >> 2;                  // 0..63
    const int c16 = tid & 3;                  // 0..3
    const unsigned sAu = smem_u32(sA), sBu = smem_u32(sB);
    const unsigned so0 = (unsigned)(r0 * A_STRIDE + c16 * 16);
    const unsigned so1 = (unsigned)((r0 + 64) * A_STRIDE + c16 * 16);
    const char* aSrc0 = reinterpret_cast<const char*>(
        g_zh + (size_t)(rowBase + r0) * DIM) + c16 * 16;
    const char* aSrc1 = aSrc0 + (size_t)64 * DIM * 2;

    for (int chunk = 0; chunk < 8; chunk++) {
        const int ct = chunk * 128;
        const char* bSrc0 = reinterpret_cast<const char*>(
            g_eh + (size_t)(ct + r0) * DIM) + c16 * 16;
        const char* bSrc1 = bSrc0 + (size_t)64 * DIM * 2;

        float acc[4][4][4];
#pragma unroll
        for (int mi = 0; mi < 4; mi++)
#pragma unroll
            for (int ni = 0; ni < 4; ni++)
#pragma unroll
                for (int q = 0; q < 4; q++)
                    acc[mi][ni][q] = 0.0f;

        // Preload k-tile 0 into buffer 0 (buf0's last readers are behind the
        // kt=6 barrier of the previous chunk).
        CP_ASYNC16(sAu + so0, aSrc0);
        CP_ASYNC16(sAu + so1, aSrc1);
        CP_ASYNC16(sBu + so0, bSrc0);
        CP_ASYNC16(sBu + so1, bSrc1);
        CP_COMMIT();
        CP_WAIT0();
        __syncthreads();

        for (int kt = 0; kt < 8; kt++) {
            if (kt < 7) {   // async-load next k-tile into the other buffer
                const unsigned bo = (unsigned)(((kt + 1) & 1) * TILE_B);
                const int ko = (kt + 1) * 64;   // bytes (32 bf16)
                CP_ASYNC16(sAu + bo + so0, aSrc0 + ko);
                CP_ASYNC16(sAu + bo + so1, aSrc1 + ko);
                CP_ASYNC16(sBu + bo + so0, bSrc0 + ko);
                CP_ASYNC16(sBu + bo + so1, bSrc1 + ko);
                CP_COMMIT();
            }

            const unsigned bo = (unsigned)((kt & 1) * TILE_B);
#pragma unroll
            for (int ks = 0; ks < 2; ks++) {
                unsigned b0[4], b1[4];
                LDSM_X4(b0[0], b0[1], b0[2], b0[3],
                        bB + bo + 0 * (16 * A_STRIDE) + ks * 32);
                LDSM_X4(b1[0], b1[1], b1[2], b1[3],
                        bB + bo + 1 * (16 * A_STRIDE) + ks * 32);
#pragma unroll
                for (int mi = 0; mi < 4; mi++) {
                    unsigned a0, a1, a2, a3;
                    LDSM_X4(a0, a1, a2, a3,
                            aB + bo + mi * (16 * A_STRIDE) + ks * 32);
                    MMA_BF16(acc[mi][0], a0, a1, a2, a3, b0[0], b0[1]);
                    MMA_BF16(acc[mi][1], a0, a1, a2, a3, b0[2], b0[3]);
                    MMA_BF16(acc[mi][2], a0, a1, a2, a3, b1[0], b1[1]);
                    MMA_BF16(acc[mi][3], a0, a1, a2, a3, b1[2], b1[3]);
                }
            }

            if (kt < 7) {
                CP_WAIT0();
                __syncthreads();
            }
        }

        // ---- Epilogue: dist = Se - 2*dot (Sz row-constant, dropped) ----
        const int colb = wn * 32 + ((lane & 3) << 1);   // chunk-local column
#pragma unroll
        for (int mi = 0; mi < 4; mi++)
#pragma unroll
            for (int ni = 0; ni < 4; ni++) {
                float se0 = ses[ct + colb + ni * 8];
                float se1 = ses[ct + colb + ni * 8 + 1];
                acc[mi][ni][0] = fmaf(-2.0f, acc[mi][ni][0], se0);
                acc[mi][ni][1] = fmaf(-2.0f, acc[mi][ni][1], se1);
                acc[mi][ni][2] = fmaf(-2.0f, acc[mi][ni][2], se0);
                acc[mi][ni][3] = fmaf(-2.0f, acc[mi][ni][3], se1);
            }

        // Step 1: quad-shfl min across the 4 lanes owning each row, then ONE
        // shared atomicMin per row per warp (lanes 0,4,...,28 active; distinct
        // rows -> distinct banks -> no serialization).
#pragma unroll
        for (int mi = 0; mi < 4; mi++)
#pragma unroll
            for (int h = 0; h < 2; h++) {
                float lm = 3.0e38f;
#pragma unroll
                for (int ni = 0; ni < 4; ni++) {
                    lm = fminf(lm, acc[mi][ni][h * 2]);
                    lm = fminf(lm, acc[mi][ni][h * 2 + 1]);
                }
                lm = fminf(lm, __shfl_xor_sync(0xffffffffu, lm, 1));
                lm = fminf(lm, __shfl_xor_sync(0xffffffffu, lm, 2));
                if ((lane & 3) == 0)
                    atomicMin(&rowMinK[wm * 64 + mi * 16 + h * 8 + (lane >> 2)],
                              fkey(lm));
            }
        __syncthreads();

        // Step 2: record codes within MARGIN of the prefix min (+ dist).
        // No trailing sync: rowMinK only decreases; a stale (larger) threshold
        // records extra candidates, never drops the winner.
#pragma unroll
        for (int mi = 0; mi < 4; mi++)
#pragma unroll
            for (int h = 0; h < 2; h++) {
                int   lrow = wm * 64 + mi * 16 + h * 8 + (lane >> 2);
                float th   = funkey(rowMinK[lrow]) + MARGIN;
                int   grow = rowBase + lrow;
#pragma unroll
                for (int ni = 0; ni < 4; ni++)
#pragma unroll
                    for (int j = 0; j < 2; j++) {
                        float d = acc[mi][ni][h * 2 + j];
                        if (d < th) {
                            int s = atomicAdd(&g_candCnt[grow], 1);
                            if (s < CAND_CAP) {
                                g_cand[grow * CAND_CAP + s] =
                                    ct + colb + ni * 8 + j;
                                g_candDist[grow * CAND_CAP + s] = d;
                            }
                        }
                    }
            }
    }

    // Publish final per-row approx min (complete after last step-1 barrier)
    if (tid < 128) g_rowMin[rowBase + tid] = funkey(rowMinK[tid]);
}

// ---------------------------------------------------------------------------
// Fused refine + gather + loss. One warp per row.
// Refine: filter candidates vs FINAL approx row min; single survivor -> done;
// several -> warp-cooperative exact fp32 dots (t = fl(Sz+Se),
// dist = fmaf(-2,dot,t), lex (dist,idx) min); empty/overflow -> full exact
// scan. Then gather: out = z + (q - z) (R3-identical arithmetic) + loss
// partials (deterministic, no atomics).
// ---------------------------------------------------------------------------
__global__ void __launch_bounds__(256)
refine_gather_kernel(const float* __restrict__ z, const float* __restrict__ e,
                     float* __restrict__ out_zq, float* __restrict__ out_idx)
{
    __shared__ float ws[8];
    int warp = threadIdx.x >> 5;
    int lane = threadIdx.x & 31;
    int row  = blockIdx.x * 8 + warp;

    int  m = g_candCnt[row];
    bool fullscan = (m > CAND_CAP);
    float bd = 3.0e38f;
    int   bc = 0;                       // valid fallback code

    if (!fullscan) {
        float th   = g_rowMin[row] + MARGIN;
        int   code = 0;
        bool  eff  = false;
        if (lane < m) {
            code = g_cand[(size_t)row * CAND_CAP + lane];
            eff  = g_candDist[(size_t)row * CAND_CAP + lane] < th;
        }
        unsigned mask = __ballot_sync(0xffffffffu, eff);
        int pc = __popc(mask);
        if (pc == 1) {
            bc = __shfl_sync(0xffffffffu, code, __ffs(mask) - 1);
        } else if (pc == 0) {
            fullscan = true;            // defensive: degrade, never garbage
        } else {
            float sz = g_Sz[row];
            const float4* zp =
                reinterpret_cast<const float4*>(z + (size_t)row * DIM);
            float4 z0 = zp[lane * 2];
            float4 z1 = zp[lane * 2 + 1];
            for (unsigned mm = mask; mm; mm &= (mm - 1)) {
                int i = __ffs(mm) - 1;
                int c = __shfl_sync(0xffffffffu, code, i);
                const float4* ep =
                    reinterpret_cast<const float4*>(e + (size_t)c * DIM);
                float4 e0 = ep[lane * 2];
                float4 e1 = ep[lane * 2 + 1];
                float acc = 0.0f;
                acc = fmaf(z0.x, e0.x, acc); acc = fmaf(z0.y, e0.y, acc);
                acc = fmaf(z0.z, e0.z, acc); acc = fmaf(z0.w, e0.w, acc);
                acc = fmaf(z1.x, e1.x, acc); acc = fmaf(z1.y, e1.y, acc);
                acc = fmaf(z1.z, e1.z, acc); acc = fmaf(z1.w, e1.w, acc);
#pragma unroll
                for (int s = 16; s >= 1; s >>= 1)
                    acc += __shfl_xor_sync(0xffffffffu, acc, s);
                float t    = sz + g_Se[c];
                float dist = fmaf(-2.0f, acc, t);
                if (dist < bd || (dist == bd && c < bc)) { bd = dist; bc = c; }
            }
            // all lanes hold identical (bd, bc)
        }
    }

    if (fullscan) {                     // overflow / defensive path
        float sz = g_Sz[row];
        const float* zr = z + (size_t)row * DIM;
        bd = 3.0e38f;
        bc = 0;
        for (int c = lane; c < KCODES; c += 32) {
            const float* er = e + (size_t)c * DIM;
            float acc = 0.0f;
#pragma unroll 8
            for (int k = 0; k < DIM; k++)
                acc = fmaf(zr[k], er[k], acc);
            float t    = sz + g_Se[c];
            float dist = fmaf(-2.0f, acc, t);
            if (dist < bd || (dist == bd && c < bc)) { bd = dist; bc = c; }
        }
#pragma unroll
        for (int s = 16; s >= 1; s >>= 1) {
            float od = __shfl_xor_sync(0xffffffffu, bd, s);
            int   oc = __shfl_xor_sync(0xffffffffu, bc, s);
            if (od < bd || (od == bd && oc < bc)) { bd = od; bc = oc; }
        }
    }

    // ---- Gather (R3-identical arithmetic) + loss partial ----
    const float4* zp = reinterpret_cast<const float4*>(z + (size_t)row * DIM);
    const float4* qp = reinterpret_cast<const float4*>(e + (size_t)bc * DIM);
    float4*       op = reinterpret_cast<float4*>(out_zq + (size_t)row * DIM);

    float local = 0.0f;
#pragma unroll
    for (int t = 0; t < 2; t++) {
        int c = lane + t * 32;
        float4 zv = zp[c];
        float4 qv = qp[c];
        float dx = qv.x - zv.x, dy = qv.y - zv.y;
        float dz2 = qv.z - zv.z, dw = qv.w - zv.w;
        float4 o = make_float4(zv.x + dx, zv.y + dy, zv.z + dz2, zv.w + dw);
        op[c] = o;
        local += dx * dx + dy * dy + dz2 * dz2 + dw * dw;
    }
#pragma unroll
    for (int s = 16; s >= 1; s >>= 1)
        local += __shfl_xor_sync(0xffffffffu, local, s);

    if (lane == 0) {
        ws[warp] = local;
        if (out_idx) out_idx[row] = (float)bc;
    }
    __syncthreads();
    if (threadIdx.x == 0) {
        float s = 0.0f;
#pragma unroll
        for (int w = 0; w < 8; w++) s += ws[w];
        g_partials[blockIdx.x] = s;
    }
}

__global__ void __launch_bounds__(256)
finalize_kernel(float* __restrict__ out_loss)
{
    __shared__ float sm[256];
    float s = 0.0f;
    for (int i = threadIdx.x; i < NROWS / 8; i += 256)
        s += g_partials[i];
    sm[threadIdx.x] = s;
    __syncthreads();
    for (int m = 128; m >= 1; m >>= 1) {
        if (threadIdx.x < m) sm[threadIdx.x] += sm[threadIdx.x + m];
        __syncthreads();
    }
    if (threadIdx.x == 0) {
        float mean = sm[0] / 16777216.0f;
        out_loss[0] = mean + 0.25f * mean;
    }
}

// ---------------------------------------------------------------------------
// kernel_launch: ONLY kernel launches (no other runtime API calls).
// ---------------------------------------------------------------------------
extern "C" void kernel_launch(void* const* d_in, const int* in_sizes, int n_in,
                              void* d_out, int out_size)
{
    const float* z = (const float*)d_in[0];   // (65536, 1, 256) fp32
    const float* e = (const float*)d_in[1];   // (1024, 256) fp32
    float* out = (float*)d_out;

    float* out_zq   = out;
    float* out_idx  = nullptr;
    float* out_loss = nullptr;
    long long total = (long long)out_size;
    const long long ZQ = (long long)NROWS * DIM;
    if (total >= ZQ + NROWS)     out_idx  = out + ZQ;
    if (total >= ZQ + NROWS + 1) out_loss = out + ZQ + NROWS;

    convert_z_kernel<<<NROWS / 8, 256>>>(z);
    convert_e_kernel<<<KCODES / 8, 256>>>(e);
    mma_cand_kernel<<<NROWS / 128, 256>>>();
    refine_gather_kernel<<<NROWS / 8, 256>>>(z, e, out_zq, out_idx);
    if (out_loss) finalize_kernel<<<1, 256>>>(out_loss);
}